// round 16
// baseline (speedup 1.0000x reference)
#include <cuda_runtime.h>
#include <cuda_bf16.h>
#include <mma.h>
#include <cstdint>
using namespace nvcuda;

#define TT 512
#define BB 128
#define II 256
#define HH 512
#define NCTA 128      // 64 H-tiles x 2 batch-halves; all co-resident
#define NTHR 256

#define WLD 776                         // 1552B row %128 = 16 -> conflict-free
#define VLD 72                          // 144B row  %128 = 16 -> conflict-free
#define GLD 68
#define SM_BIAS 0                       // 32 floats
#define SM_W    128
#define WBYTES  (2*32*WLD*2)            // 99328: [hl][32 rows][776] bf16
#define SM_V0   (SM_W + WBYTES)         // 99456
#define VBUF_B  (2*2*64*VLD*2)          // 36864: [half][hl][64 b][72] bf16
#define VBUF_E  (VBUF_B/2)
#define SM_GSM  (SM_V0 + 3*VBUF_B)      // 210048: [kh 2][32 m][GLD] fp32
#define SMEM_BYTES (SM_GSM + 2*32*GLD*4)  // 227456 <= 232448 cap

// Device scratch (static — no allocations).
__device__ __align__(16) __nv_bfloat16 g_Wsplit[64ULL * 2 * 32 * 768];        // 6.3MB
__device__ __align__(16) __nv_bfloat16 g_xsplit[(size_t)TT * 2 * BB * II];    // 67MB
__device__ __align__(16) __nv_bfloat16 g_hsplit[2 * 2 * BB * HH];             // 512KB
__device__ unsigned g_bar;

#define CP16(dst, src, sz) \
    asm volatile("cp.async.cg.shared.global [%0], [%1], 16, %2;" \
                 :: "r"(dst), "l"(src), "r"(sz) : "memory")
#define CP_COMMIT() asm volatile("cp.async.commit_group;")
#define CP_WAIT(n)  asm volatile("cp.async.wait_group %0;" :: "n"(n) : "memory")

// Chunk c -> two 64-k windows. Chunks 0,1 are pure-x (prefetchable across the
// grid barrier); chunks 2..5 carry the h-dependent windows.
__device__ __forceinline__ int win0(int c) { return (c < 2) ? 8 + c : c - 2; }   // kh=0
__device__ __forceinline__ int win1(int c) { return (c < 2) ? 10 + c : c + 2; }  // kh=1

__device__ __forceinline__ float fsigm(float x) {
    float e; asm("ex2.approx.f32 %0, %1;" : "=f"(e) : "f"(-1.4426950408889634f * x));
    float r; asm("rcp.approx.f32 %0, %1;" : "=f"(r) : "f"(1.0f + e));
    return r;
}
__device__ __forceinline__ float ftanh(float x) {
    float ax = fabsf(x);
    float e; asm("ex2.approx.f32 %0, %1;" : "=f"(e) : "f"(-2.885390081777927f * ax));
    float r; asm("rcp.approx.f32 %0, %1;" : "=f"(r) : "f"(1.0f + e));
    return copysignf((1.0f - e) * r, x);
}

// ---------------------------------------------------------------------------
// pack_W: per-H-tile A slices. Row r = g*8+jj, A[r][k] = W_g[k][hh*8+jj],
// split bf16 hi/lo planes. Resets the grid barrier.
// ---------------------------------------------------------------------------
__global__ void pack_W(const float* __restrict__ Wf, const float* __restrict__ Wi,
                       const float* __restrict__ Wc, const float* __restrict__ Wo) {
    if (blockIdx.x == 0 && blockIdx.y == 0 && threadIdx.x == 0) g_bar = 0u;
    const int hh = blockIdx.x, g = blockIdx.y;
    const float* W = (g == 0) ? Wf : (g == 1) ? Wi : (g == 2) ? Wc : Wo;
    __nv_bfloat16* base = g_Wsplit + (size_t)hh * (2 * 32 * 768);
    #pragma unroll
    for (int l = 0; l < 24; ++l) {
        const int idx = threadIdx.x + l * 256;     // 0..6143
        const int jj = idx / 768, k = idx % 768;
        const float w = W[(size_t)k * HH + hh * 8 + jj];
        const __nv_bfloat16 hi = __float2bfloat16(w);
        const __nv_bfloat16 lo = __float2bfloat16(w - __bfloat162float(hi));
        base[(0 * 32 + g * 8 + jj) * 768 + k] = hi;
        base[(1 * 32 + g * 8 + jj) * 768 + k] = lo;
    }
}

// pack_x: [t][hl][b][256] split-bf16, fully coalesced.
__global__ void pack_x(const float* __restrict__ x) {
    const int t = blockIdx.x;
    const float* xt = x + (size_t)t * (BB * II);
    __nv_bfloat16* dh = g_xsplit + ((size_t)t * 2 + 0) * (BB * II);
    __nv_bfloat16* dl = g_xsplit + ((size_t)t * 2 + 1) * (BB * II);
    #pragma unroll
    for (int l = 0; l < (BB * II) / 256; ++l) {
        const int idx = threadIdx.x + l * 256;
        const float v = xt[idx];
        const __nv_bfloat16 hi = __float2bfloat16(v);
        dh[idx] = hi;
        dl[idx] = __float2bfloat16(v - __bfloat162float(hi));
    }
}

// ---------------------------------------------------------------------------
// Stage chunk c for step t: both windows, both hl planes, 64 local batches.
// 2048 x 16B -> 8 per thread. h windows (k<512) zero-fill at t==0.
// ---------------------------------------------------------------------------
__device__ __forceinline__ void stage(uint32_t vdst, int t, int c, int tid, int nbase) {
    const int par = (t & 1) ^ 1;
    #pragma unroll
    for (int j = 0; j < 8; ++j) {
        const int idx = tid + j * NTHR;            // 0..2047
        const int seg  = idx & 7;
        const int b    = (idx >> 3) & 63;
        const int hl   = (idx >> 9) & 1;
        const int half = idx >> 10;
        const int w    = half ? win1(c) : win0(c);
        const int k0   = w * 64;
        const uint32_t d = vdst + (uint32_t)((((half * 2 + hl) * 64 + b) * VLD * 2) + seg * 16);
        if (k0 < 512) {
            const char* s = (const char*)g_hsplit
                + ((size_t)((par * 2 + hl) * 128 + nbase + b) * HH + k0 + seg * 8) * 2;
            CP16(d, s, (t == 0) ? 0 : 16);
        } else {
            const char* s = (const char*)g_xsplit
                + (((size_t)t * 2 + hl) * (BB * II) + (size_t)(nbase + b) * II
                   + (k0 - 512) + seg * 8) * 2;
            CP16(d, s, 16);
        }
    }
}

// ---------------------------------------------------------------------------
// Persistent wmma kernel. 8 warps: kh = warp>>2 (window of the chunk pair),
// nw = warp&3 (n16 of 64). mh (2 m16 tiles) unrolled inside.
// 3-stage cp.async pipeline: chunk c lives in buf c%3, one commit group each.
// ---------------------------------------------------------------------------
__global__ void __launch_bounds__(NTHR, 1)
lstm_wmma(const float* __restrict__ bf, const float* __restrict__ bi_,
          const float* __restrict__ bc, const float* __restrict__ bo,
          float* __restrict__ out)
{
    extern __shared__ char smc[];
    float* bias = (float*)(smc + SM_BIAS);
    __nv_bfloat16* Wsm = (__nv_bfloat16*)(smc + SM_W);
    __nv_bfloat16* vsm = (__nv_bfloat16*)(smc + SM_V0);
    float* gsm = (float*)(smc + SM_GSM);
    const uint32_t vsm_s = (uint32_t)__cvta_generic_to_shared(vsm);

    const int tid  = threadIdx.x;
    const int hh   = blockIdx.x >> 1;              // H-tile (8 cols)
    const int nb   = blockIdx.x & 1;               // batch half
    const int nbase = nb * 64;
    const int j0   = hh * 8;
    const int warp = tid >> 5, lane = tid & 31;
    const int kh   = warp >> 2, nw = warp & 3;

    // W slice (hi+lo, 64 rows x 768) -> smem rows with pitch WLD.
    {
        const uint4* src = (const uint4*)(g_Wsplit + (size_t)hh * (2 * 32 * 768));
        for (int rr = warp; rr < 64; rr += 8) {
            uint4* drow = (uint4*)(Wsm + rr * WLD);
            const uint4* srow = src + rr * 96;
            #pragma unroll
            for (int u = lane; u < 96; u += 32) drow[u] = srow[u];
        }
    }
    if (tid < 32) {
        const int g = tid >> 3;
        const float* bp = (g == 0) ? bf : (g == 1) ? bi_ : (g == 2) ? bc : bo;
        bias[tid] = bp[j0 + (tid & 7)];
    }
    __syncthreads();

    float Creg[2] = {0.f, 0.f};

    wmma::fragment<wmma::matrix_a, 16, 16, 16, __nv_bfloat16, wmma::row_major> fah[2], fal[2];
    wmma::fragment<wmma::matrix_b, 16, 16, 16, __nv_bfloat16, wmma::col_major> fb;
    wmma::fragment<wmma::accumulator, 16, 16, 16, float> acc[2];

    // Prefetch chunks 0 and 1 (pure x) of t=0, one group each.
    stage(vsm_s + 0 * VBUF_B, 0, 0, tid, nbase); CP_COMMIT();
    stage(vsm_s + 1 * VBUF_B, 0, 1, tid, nbase); CP_COMMIT();

    for (int t = 0; t < TT; ++t) {
        wmma::fill_fragment(acc[0], 0.0f);
        wmma::fill_fragment(acc[1], 0.0f);

        CP_WAIT(1);              // chunk 0 ready (chunk 1 may still be in flight)
        __syncthreads();

        #pragma unroll 1
        for (int i = 0; i < 6; ++i) {
            if (i < 4) {         // stage chunk i+2 into buf (i+2)%3 (freed at iter i-1)
                stage(vsm_s + (uint32_t)(((i + 2) % 3) * VBUF_B), t, i + 2, tid, nbase);
                CP_COMMIT();
            }
            const __nv_bfloat16* vb = vsm + (i % 3) * VBUF_E;
            const int w = kh ? win1(i) : win0(i);
            #pragma unroll
            for (int kt = 0; kt < 4; ++kt) {
                const int kg = w * 64 + kt * 16;
                #pragma unroll
                for (int mh = 0; mh < 2; ++mh) {
                    wmma::load_matrix_sync(fah[mh], Wsm + mh * (16 * WLD) + kg, WLD);
                    wmma::load_matrix_sync(fal[mh], Wsm + (32 + mh * 16) * WLD + kg, WLD);
                }
                const __nv_bfloat16* bh = vb + ((kh * 2 + 0) * 64 + nw * 16) * VLD + kt * 16;
                const __nv_bfloat16* bl = vb + ((kh * 2 + 1) * 64 + nw * 16) * VLD + kt * 16;
                wmma::load_matrix_sync(fb, bh, VLD);
                wmma::mma_sync(acc[0], fah[0], fb, acc[0]);
                wmma::mma_sync(acc[1], fah[1], fb, acc[1]);
                wmma::mma_sync(acc[0], fal[0], fb, acc[0]);
                wmma::mma_sync(acc[1], fal[1], fb, acc[1]);
                wmma::load_matrix_sync(fb, bl, VLD);
                wmma::mma_sync(acc[0], fah[0], fb, acc[0]);
                wmma::mma_sync(acc[1], fah[1], fb, acc[1]);
            }
            // Ensure chunk i+1 is complete before next iteration's compute.
            if (i < 4)      CP_WAIT(1);
            else if (i == 4) CP_WAIT(0);
            if (i < 5) __syncthreads();
        }

        // Partial store per kh, then combine.
        #pragma unroll
        for (int mh = 0; mh < 2; ++mh)
            wmma::store_matrix_sync(gsm + kh * (32 * GLD) + (mh * 16) * GLD + nw * 16,
                                    acc[mh], GLD, wmma::mem_row_major);
        __syncthreads();

        // Cell update: 512 cells (8 jj x 64 b), 2 per thread; C in registers.
        const int par = t & 1;
        #pragma unroll
        for (int e = 0; e < 2; ++e) {
            const int cell = tid + e * NTHR;
            const int b = cell & 63, jj = cell >> 6;
            float gate[4];
            #pragma unroll
            for (int g = 0; g < 4; ++g)
                gate[g] = gsm[(g * 8 + jj) * GLD + b]
                        + gsm[32 * GLD + (g * 8 + jj) * GLD + b]
                        + bias[g * 8 + jj];
            const float Cnew = fsigm(gate[0]) * Creg[e] + fsigm(gate[1]) * ftanh(gate[2]);
            Creg[e] = Cnew;
            const float h = fsigm(gate[3]) * ftanh(Cnew);
            const int bg = nbase + b, jg = j0 + jj;
            out[(size_t)t * (BB * HH) + (size_t)bg * HH + jg] = h;
            const __nv_bfloat16 hi = __float2bfloat16(h);
            const __nv_bfloat16 lo = __float2bfloat16(h - __bfloat162float(hi));
            g_hsplit[(size_t)((par * 2 + 0) * 128 + bg) * HH + jg] = hi;
            g_hsplit[(size_t)((par * 2 + 1) * 128 + bg) * HH + jg] = lo;
        }

        if (t < TT - 1) {
            __syncthreads();
            // Prefetch BOTH pure-x chunks of t+1 across the barrier
            // (buf0/buf1 were last computed at i=3/i=4 — free).
            stage(vsm_s + 0 * VBUF_B, t + 1, 0, tid, nbase); CP_COMMIT();
            stage(vsm_s + 1 * VBUF_B, t + 1, 1, tid, nbase); CP_COMMIT();
            if (tid == 0) {
                asm volatile("red.release.gpu.global.add.u32 [%0], %1;"
                             :: "l"(&g_bar), "r"(1u) : "memory");
                const unsigned target = (unsigned)NCTA * (unsigned)(t + 1);
                unsigned v;
                do {
                    asm volatile("ld.acquire.gpu.global.u32 %0, [%1];"
                                 : "=r"(v) : "l"(&g_bar) : "memory");
                } while (v < target);
            }
            __syncthreads();
        }
    }
}

// ---------------------------------------------------------------------------
extern "C" void kernel_launch(void* const* d_in, const int* in_sizes, int n_in,
                              void* d_out, int out_size) {
    (void)in_sizes; (void)n_in; (void)out_size;
    const float* x  = (const float*)d_in[0];
    const float* Wf = (const float*)d_in[1];
    const float* bf = (const float*)d_in[2];
    const float* Wi = (const float*)d_in[3];
    const float* bi = (const float*)d_in[4];
    const float* Wc = (const float*)d_in[5];
    const float* bc = (const float*)d_in[6];
    const float* Wo = (const float*)d_in[7];
    const float* bo = (const float*)d_in[8];
    float* out = (float*)d_out;

    cudaFuncSetAttribute(lstm_wmma, cudaFuncAttributeMaxDynamicSharedMemorySize, SMEM_BYTES);

    pack_W<<<dim3(64, 4), 256>>>(Wf, Wi, Wc, Wo);      // also resets g_bar
    pack_x<<<TT, 256>>>(x);
    lstm_wmma<<<NCTA, NTHR, SMEM_BYTES>>>(bf, bi, bc, bo, out);
}

// round 17
// speedup vs baseline: 1.0923x; 1.0923x over previous
#include <cuda_runtime.h>
#include <cuda_bf16.h>
#include <mma.h>
#include <cstdint>
using namespace nvcuda;

#define TT 512
#define BB 128
#define II 256
#define HH 512
#define NCTA 128      // 64 H-tiles x 2 batch-halves; all co-resident
#define NTHR 256

#define WLD 776                         // 1552B row %128 = 16 -> conflict-free
#define VLD 72                          // b-pitch of k-rows: 144B %128 = 16 -> conflict-free
#define GLD 68
#define SM_BIAS 0                       // 32 floats
#define SM_W    128
#define WBYTES  (2*32*WLD*2)            // 99328: [hl][32 rows][776] bf16
#define SM_V0   (SM_W + WBYTES)         // 99456
#define VBUF_B  (2*2*64*VLD*2)          // 36864: [half][hl][64 k][72 b] bf16
#define VBUF_E  (VBUF_B/2)
#define SM_GSM  (SM_V0 + 2*VBUF_B)      // 173184: [kh 2][32 m][GLD] fp32
#define SMEM_BYTES (SM_GSM + 2*32*GLD*4)  // 190592

// Device scratch (static — no allocations).
__device__ __align__(16) __nv_bfloat16 g_Wsplit[64ULL * 2 * 32 * 768];        // 6.3MB
__device__ __align__(16) __nv_bfloat16 g_xsplit[(size_t)TT * 2 * II * BB];    // 67MB  [t][hl][k][b]
__device__ __align__(16) __nv_bfloat16 g_hsplit[2 * 2 * HH * BB];             // 512KB [par][hl][k][b]
__device__ unsigned g_bar;

#define CP16(dst, src, sz) \
    asm volatile("cp.async.cg.shared.global [%0], [%1], 16, %2;" \
                 :: "r"(dst), "l"(src), "r"(sz) : "memory")
#define CP_COMMIT() asm volatile("cp.async.commit_group;")
#define CP_WAIT0()  asm volatile("cp.async.wait_group 0;" ::: "memory")

// Chunk c -> two 64-k windows. Chunks 0,1 are pure-x (prefetchable across the
// grid barrier); chunks 2..5 carry the h-dependent windows.
__device__ __forceinline__ int win0(int c) { return (c < 2) ? 8 + c : c - 2; }   // kh=0
__device__ __forceinline__ int win1(int c) { return (c < 2) ? 10 + c : c + 2; }  // kh=1

__device__ __forceinline__ float fsigm(float x) {
    float e; asm("ex2.approx.f32 %0, %1;" : "=f"(e) : "f"(-1.4426950408889634f * x));
    float r; asm("rcp.approx.f32 %0, %1;" : "=f"(r) : "f"(1.0f + e));
    return r;
}
__device__ __forceinline__ float ftanh(float x) {
    float ax = fabsf(x);
    float e; asm("ex2.approx.f32 %0, %1;" : "=f"(e) : "f"(-2.885390081777927f * ax));
    float r; asm("rcp.approx.f32 %0, %1;" : "=f"(r) : "f"(1.0f + e));
    return copysignf((1.0f - e) * r, x);
}

// ---------------------------------------------------------------------------
// pack_W: per-H-tile A slices. Row r = g*8+jj, A[r][k] = W_g[k][hh*8+jj],
// split bf16 hi/lo planes. Resets the grid barrier.
// ---------------------------------------------------------------------------
__global__ void pack_W(const float* __restrict__ Wf, const float* __restrict__ Wi,
                       const float* __restrict__ Wc, const float* __restrict__ Wo) {
    if (blockIdx.x == 0 && blockIdx.y == 0 && threadIdx.x == 0) g_bar = 0u;
    const int hh = blockIdx.x, g = blockIdx.y;
    const float* W = (g == 0) ? Wf : (g == 1) ? Wi : (g == 2) ? Wc : Wo;
    __nv_bfloat16* base = g_Wsplit + (size_t)hh * (2 * 32 * 768);
    #pragma unroll
    for (int l = 0; l < 24; ++l) {
        const int idx = threadIdx.x + l * 256;     // 0..6143
        const int jj = idx / 768, k = idx % 768;
        const float w = W[(size_t)k * HH + hh * 8 + jj];
        const __nv_bfloat16 hi = __float2bfloat16(w);
        const __nv_bfloat16 lo = __float2bfloat16(w - __bfloat162float(hi));
        base[(0 * 32 + g * 8 + jj) * 768 + k] = hi;
        base[(1 * 32 + g * 8 + jj) * 768 + k] = lo;
    }
}

// pack_x: transpose to [t][hl][k 256][b 128] via 32x33 smem tile (coalesced
// both sides, one-time).
__global__ void pack_x(const float* __restrict__ x) {
    __shared__ float tile[32][33];
    const int t = blockIdx.x, iy = blockIdx.y;     // k-tile of 32
    const int tx = threadIdx.x & 31, ty0 = threadIdx.x >> 5;
    __nv_bfloat16* dh = g_xsplit + ((size_t)t * 2 + 0) * (II * BB);
    __nv_bfloat16* dl = g_xsplit + ((size_t)t * 2 + 1) * (II * BB);
    for (int bt = 0; bt < 4; ++bt) {               // batch tiles of 32
        #pragma unroll
        for (int ty = ty0; ty < 32; ty += 8)
            tile[ty][tx] = x[((size_t)t * BB + bt * 32 + ty) * II + iy * 32 + tx];
        __syncthreads();
        #pragma unroll
        for (int ty = ty0; ty < 32; ty += 8) {
            const float v = tile[tx][ty];          // b = bt*32+tx, k = iy*32+ty
            const __nv_bfloat16 hi = __float2bfloat16(v);
            dh[(iy * 32 + ty) * BB + bt * 32 + tx] = hi;
            dl[(iy * 32 + ty) * BB + bt * 32 + tx] = __float2bfloat16(v - __bfloat162float(hi));
        }
        __syncthreads();
    }
}

// ---------------------------------------------------------------------------
// Stage chunk c for step t: both windows, both hl planes, 64 k-rows x 64 b.
// 2048 x 16B -> 8 per thread. h windows (k<512) zero-fill at t==0.
// ---------------------------------------------------------------------------
__device__ __forceinline__ void stage(uint32_t vdst, int t, int c, int tid, int nbase) {
    const int par = (t & 1) ^ 1;
    #pragma unroll
    for (int j = 0; j < 8; ++j) {
        const int idx = tid + j * NTHR;            // 0..2047
        const int seg  = idx & 7;                  // 16B segment of 128B k-row
        const int kr   = (idx >> 3) & 63;
        const int hl   = (idx >> 9) & 1;
        const int half = idx >> 10;
        const int w    = half ? win1(c) : win0(c);
        const int k0   = w * 64;
        const uint32_t d = vdst + (uint32_t)((((half * 2 + hl) * 64 + kr) * VLD * 2) + seg * 16);
        if (k0 < 512) {
            const char* s = (const char*)g_hsplit
                + (((size_t)(par * 2 + hl) * HH + k0 + kr) * BB + nbase + seg * 8) * 2;
            CP16(d, s, (t == 0) ? 0 : 16);
        } else {
            const char* s = (const char*)g_xsplit
                + ((((size_t)t * 2 + hl) * II + (k0 - 512) + kr) * BB + nbase + seg * 8) * 2;
            CP16(d, s, 16);
        }
    }
}

// ---------------------------------------------------------------------------
// Persistent wmma kernel. 8 warps: kh = warp>>2 (window of the chunk pair),
// nw = warp&3 (n16 of 64). mh (2 m16 tiles) unrolled inside.
// ---------------------------------------------------------------------------
__global__ void __launch_bounds__(NTHR, 1)
lstm_wmma(const float* __restrict__ bf, const float* __restrict__ bi_,
          const float* __restrict__ bc, const float* __restrict__ bo,
          float* __restrict__ out)
{
    extern __shared__ char smc[];
    float* bias = (float*)(smc + SM_BIAS);
    __nv_bfloat16* Wsm = (__nv_bfloat16*)(smc + SM_W);
    __nv_bfloat16* vsm = (__nv_bfloat16*)(smc + SM_V0);
    float* gsm = (float*)(smc + SM_GSM);
    const uint32_t vsm_s = (uint32_t)__cvta_generic_to_shared(vsm);

    const int tid  = threadIdx.x;
    const int hh   = blockIdx.x >> 1;              // H-tile (8 cols)
    const int nb   = blockIdx.x & 1;               // batch half
    const int nbase = nb * 64;
    const int j0   = hh * 8;
    const int warp = tid >> 5, lane = tid & 31;
    const int kh   = warp >> 2, nw = warp & 3;

    // W slice (hi+lo, 64 rows x 768) -> smem rows with pitch WLD.
    {
        const uint4* src = (const uint4*)(g_Wsplit + (size_t)hh * (2 * 32 * 768));
        for (int rr = warp; rr < 64; rr += 8) {
            uint4* drow = (uint4*)(Wsm + rr * WLD);
            const uint4* srow = src + rr * 96;
            #pragma unroll
            for (int u = lane; u < 96; u += 32) drow[u] = srow[u];
        }
    }
    if (tid < 32) {
        const int g = tid >> 3;
        const float* bp = (g == 0) ? bf : (g == 1) ? bi_ : (g == 2) ? bc : bo;
        bias[tid] = bp[j0 + (tid & 7)];
    }
    __syncthreads();

    float Creg[2] = {0.f, 0.f};

    wmma::fragment<wmma::matrix_a, 16, 16, 16, __nv_bfloat16, wmma::row_major> fah[2], fal[2];
    wmma::fragment<wmma::matrix_b, 16, 16, 16, __nv_bfloat16, wmma::row_major> fb;
    wmma::fragment<wmma::accumulator, 16, 16, 16, float> acc[2];

    // Prefetch chunk 0 (pure x) of t=0.
    stage(vsm_s, 0, 0, tid, nbase);
    CP_COMMIT();

    for (int t = 0; t < TT; ++t) {
        wmma::fill_fragment(acc[0], 0.0f);
        wmma::fill_fragment(acc[1], 0.0f);

        CP_WAIT0();
        __syncthreads();

        #pragma unroll 1
        for (int i = 0; i < 6; ++i) {
            const int buf = i & 1;
            if (i < 5) {
                stage(vsm_s + (uint32_t)((buf ^ 1) * VBUF_B), t, i + 1, tid, nbase);
                CP_COMMIT();
            }
            const __nv_bfloat16* vb = vsm + buf * VBUF_E;
            const int w = kh ? win1(i) : win0(i);
            #pragma unroll
            for (int kt = 0; kt < 4; ++kt) {
                const int kg = w * 64 + kt * 16;
                #pragma unroll
                for (int mh = 0; mh < 2; ++mh) {
                    wmma::load_matrix_sync(fah[mh], Wsm + mh * (16 * WLD) + kg, WLD);
                    wmma::load_matrix_sync(fal[mh], Wsm + (32 + mh * 16) * WLD + kg, WLD);
                }
                // B row-major [k][b]: tile (k = kt*16.., n = nw*16..)
                const __nv_bfloat16* bh = vb + ((kh * 2 + 0) * 64 + kt * 16) * VLD + nw * 16;
                const __nv_bfloat16* bl = vb + ((kh * 2 + 1) * 64 + kt * 16) * VLD + nw * 16;
                wmma::load_matrix_sync(fb, bh, VLD);
                wmma::mma_sync(acc[0], fah[0], fb, acc[0]);
                wmma::mma_sync(acc[1], fah[1], fb, acc[1]);
                wmma::mma_sync(acc[0], fal[0], fb, acc[0]);
                wmma::mma_sync(acc[1], fal[1], fb, acc[1]);
                wmma::load_matrix_sync(fb, bl, VLD);
                wmma::mma_sync(acc[0], fah[0], fb, acc[0]);
                wmma::mma_sync(acc[1], fah[1], fb, acc[1]);
            }
            if (i < 5) {
                CP_WAIT0();
                __syncthreads();
            }
        }

        // Partial store per kh, then combine.
        #pragma unroll
        for (int mh = 0; mh < 2; ++mh)
            wmma::store_matrix_sync(gsm + kh * (32 * GLD) + (mh * 16) * GLD + nw * 16,
                                    acc[mh], GLD, wmma::mem_row_major);
        __syncthreads();

        // Cell update: 512 cells (8 jj x 64 b), 2/thread. jj fast in lane ->
        // out stores 32B-contiguous per 8 lanes; h stores contiguous per k-row.
        const int par = t & 1;
        const int jj = tid & 7, bq = tid >> 3;
        const int jg = j0 + jj;
        #pragma unroll
        for (int e = 0; e < 2; ++e) {
            const int b = bq + e * 32;
            float gate[4];
            #pragma unroll
            for (int g = 0; g < 4; ++g)
                gate[g] = gsm[(g * 8 + jj) * GLD + b]
                        + gsm[32 * GLD + (g * 8 + jj) * GLD + b]
                        + bias[g * 8 + jj];
            const float Cnew = fsigm(gate[0]) * Creg[e] + fsigm(gate[1]) * ftanh(gate[2]);
            Creg[e] = Cnew;
            const float h = fsigm(gate[3]) * ftanh(Cnew);
            const int bg = nbase + b;
            out[(size_t)t * (BB * HH) + (size_t)bg * HH + jg] = h;
            const __nv_bfloat16 hi = __float2bfloat16(h);
            const __nv_bfloat16 lo = __float2bfloat16(h - __bfloat162float(hi));
            g_hsplit[((size_t)(par * 2 + 0) * HH + jg) * BB + bg] = hi;
            g_hsplit[((size_t)(par * 2 + 1) * HH + jg) * BB + bg] = lo;
        }

        if (t < TT - 1) {
            __syncthreads();
            // Prefetch next step's chunk 0 (pure x) across the barrier.
            stage(vsm_s, t + 1, 0, tid, nbase);
            CP_COMMIT();
            if (tid == 0) {
                asm volatile("red.release.gpu.global.add.u32 [%0], %1;"
                             :: "l"(&g_bar), "r"(1u) : "memory");
                const unsigned target = (unsigned)NCTA * (unsigned)(t + 1);
                unsigned v;
                do {
                    asm volatile("ld.acquire.gpu.global.u32 %0, [%1];"
                                 : "=r"(v) : "l"(&g_bar) : "memory");
                } while (v < target);
            }
            __syncthreads();
        }
    }
}

// ---------------------------------------------------------------------------
extern "C" void kernel_launch(void* const* d_in, const int* in_sizes, int n_in,
                              void* d_out, int out_size) {
    (void)in_sizes; (void)n_in; (void)out_size;
    const float* x  = (const float*)d_in[0];
    const float* Wf = (const float*)d_in[1];
    const float* bf = (const float*)d_in[2];
    const float* Wi = (const float*)d_in[3];
    const float* bi = (const float*)d_in[4];
    const float* Wc = (const float*)d_in[5];
    const float* bc = (const float*)d_in[6];
    const float* Wo = (const float*)d_in[7];
    const float* bo = (const float*)d_in[8];
    float* out = (float*)d_out;

    cudaFuncSetAttribute(lstm_wmma, cudaFuncAttributeMaxDynamicSharedMemorySize, SMEM_BYTES);

    pack_W<<<dim3(64, 4), 256>>>(Wf, Wi, Wc, Wo);      // also resets g_bar
    pack_x<<<dim3(TT, 8), 256>>>(x);
    lstm_wmma<<<NCTA, NTHR, SMEM_BYTES>>>(bf, bi, bc, bo, out);
}